// round 6
// baseline (speedup 1.0000x reference)
#include <cuda_runtime.h>
#include <cuda_fp16.h>

// GCNConv, CSR-gather with fp16 feature matrix and fused preprocessing:
//   s1 : k_gemm      h_half = fp16(x @ W^T)
//   s0 : k_init      cnt=0, deg=1
//        k_edge      rank[i]=atomicAdd(cnt[dst]); atomicAdd(deg[dst], ew)  (fused)
//        k_scan      1-block shfl scan -> off; also dinv = rsqrt(deg)
//        k_build     edge[off[dst]+rank] = {src, dinv_s*ew*dinv_d}
//   join k_aggregate out = dinv^2*h[i] + sum h[src]*w + b   (fp32 accum)

#define MAX_NODES 10016
#define MAX_EDGES 650000
#define D 128

__device__ float  g_deg[MAX_NODES];
__device__ float  g_dinv[MAX_NODES];
__device__ __half g_hh[(size_t)MAX_NODES * D];
__device__ int    g_cnt[MAX_NODES];
__device__ int    g_off[MAX_NODES + 1];
__device__ int    g_rank[MAX_EDGES];
__device__ int2   g_edge[MAX_EDGES];   // {src, float_bits(dinv_s*ew*dinv_d)}

// ---------------------------------------------------------------------------
__global__ void k_init(int n) {
    int i = blockIdx.x * blockDim.x + threadIdx.x;
    if (i < n) { g_cnt[i] = 0; g_deg[i] = 1.0f; }
}

// Fused histogram (rank capture) + weighted degree. 4 edges per thread.
__global__ void k_edge(const float* __restrict__ ew,
                       const int* __restrict__ dst, int e) {
    int i4 = (blockIdx.x * blockDim.x + threadIdx.x) * 4;
    if (i4 + 3 < e) {
        int4 d = *(const int4*)&dst[i4];
        float4 w = *(const float4*)&ew[i4];
        g_rank[i4 + 0] = atomicAdd(&g_cnt[d.x], 1);
        g_rank[i4 + 1] = atomicAdd(&g_cnt[d.y], 1);
        g_rank[i4 + 2] = atomicAdd(&g_cnt[d.z], 1);
        g_rank[i4 + 3] = atomicAdd(&g_cnt[d.w], 1);
        atomicAdd(&g_deg[d.x], w.x);
        atomicAdd(&g_deg[d.y], w.y);
        atomicAdd(&g_deg[d.z], w.z);
        atomicAdd(&g_deg[d.w], w.w);
    } else {
        for (int i = i4; i < e; i++) {
            int d = dst[i];
            g_rank[i] = atomicAdd(&g_cnt[d], 1);
            atomicAdd(&g_deg[d], ew[i]);
        }
    }
}

// Single-block scan + dinv. 1024 threads x CHUNK elements, 2 barriers.
#define CHUNK 10   // 1024*10 = 10240 >= MAX_NODES
__global__ void k_scan(int n) {
    int tid = threadIdx.x;
    int lane = tid & 31, wid = tid >> 5;
    int base = tid * CHUNK;

    int v[CHUNK];
    int sum = 0;
#pragma unroll
    for (int j = 0; j < CHUNK; j++) {
        int i = base + j;
        int c = (i < n) ? g_cnt[i] : 0;
        v[j] = sum;
        sum += c;
        if (i < n) g_dinv[i] = rsqrtf(g_deg[i]);   // fused dinv
    }
    int s = sum;
#pragma unroll
    for (int o = 1; o < 32; o <<= 1) {
        int t = __shfl_up_sync(0xffffffffu, s, o);
        if (lane >= o) s += t;
    }
    __shared__ int wsum[32];
    if (lane == 31) wsum[wid] = s;
    __syncthreads();
    if (wid == 0) {
        int w = wsum[lane];
#pragma unroll
        for (int o = 1; o < 32; o <<= 1) {
            int t = __shfl_up_sync(0xffffffffu, w, o);
            if (lane >= o) w += t;
        }
        wsum[lane] = w;
    }
    __syncthreads();
    int excl = s - sum + (wid > 0 ? wsum[wid - 1] : 0);
#pragma unroll
    for (int j = 0; j < CHUNK; j++) {
        int i = base + j;
        if (i < n) g_off[i] = excl + v[j];
    }
    if (tid == 1023) g_off[n] = excl + sum;
}

// Atomic-free CSR scatter with folded normalization.
__global__ void k_build(const float* __restrict__ ew,
                        const int* __restrict__ src,
                        const int* __restrict__ dst, int e) {
    int i = blockIdx.x * blockDim.x + threadIdx.x;
    if (i < e) {
        int s = src[i], d = dst[i];
        float w = g_dinv[s] * ew[i] * g_dinv[d];
        int p = g_off[d] + g_rank[i];
        g_edge[p] = make_int2(s, __float_as_int(w));
    }
}

// ---------------------------------------------------------------------------
// h = fp16(x @ W^T).  64 nodes x 128 dims per block, BK=16, 256 threads.
#define BM 64
#define BK 16
#define XS_LD 68
#define WS_LD 132
__global__ void k_gemm(const float* __restrict__ x, const float* __restrict__ W,
                       int n) {
    __shared__ float xs[BK][XS_LD];
    __shared__ float ws[BK][WS_LD];
    int t = threadIdx.x;
    int c = t & 31;
    int r = t >> 5;
    int node0 = blockIdx.x * BM;

    float acc[8][4];
#pragma unroll
    for (int j = 0; j < 8; j++)
#pragma unroll
        for (int i = 0; i < 4; i++) acc[j][i] = 0.0f;

    for (int k0 = 0; k0 < D; k0 += BK) {
        {
            int nn = t >> 2;
            int ks = (t & 3) * 4;
            int gn = node0 + nn;
            float4 v = make_float4(0.f, 0.f, 0.f, 0.f);
            if (gn < n) v = *(const float4*)&x[(size_t)gn * D + k0 + ks];
            xs[ks + 0][nn] = v.x; xs[ks + 1][nn] = v.y;
            xs[ks + 2][nn] = v.z; xs[ks + 3][nn] = v.w;
        }
#pragma unroll
        for (int q = 0; q < 2; q++) {
            int f = t * 2 + q;
            int dim = f >> 2;
            int ks = (f & 3) * 4;
            float4 v = *(const float4*)&W[(size_t)dim * D + k0 + ks];
            ws[ks + 0][dim] = v.x; ws[ks + 1][dim] = v.y;
            ws[ks + 2][dim] = v.z; ws[ks + 3][dim] = v.w;
        }
        __syncthreads();
#pragma unroll
        for (int kk = 0; kk < BK; kk++) {
            float4 wv = *(const float4*)&ws[kk][c * 4];
            float4 xa = *(const float4*)&xs[kk][r * 8];
            float4 xb = *(const float4*)&xs[kk][r * 8 + 4];
            float xn[8] = {xa.x, xa.y, xa.z, xa.w, xb.x, xb.y, xb.z, xb.w};
#pragma unroll
            for (int j = 0; j < 8; j++) {
                acc[j][0] += xn[j] * wv.x;
                acc[j][1] += xn[j] * wv.y;
                acc[j][2] += xn[j] * wv.z;
                acc[j][3] += xn[j] * wv.w;
            }
        }
        __syncthreads();
    }
#pragma unroll
    for (int j = 0; j < 8; j++) {
        int gn = node0 + r * 8 + j;
        if (gn < n) {
            __half2 p0 = __floats2half2_rn(acc[j][0], acc[j][1]);
            __half2 p1 = __floats2half2_rn(acc[j][2], acc[j][3]);
            uint2 u;
            u.x = *(unsigned int*)&p0;
            u.y = *(unsigned int*)&p1;
            ((uint2*)(g_hh + (size_t)gn * D))[c] = u;
        }
    }
}

// ---------------------------------------------------------------------------
// One warp per destination node; fp32 accumulator, fp16 gathers (8B/lane).
__global__ void k_aggregate(const float* __restrict__ b, float* __restrict__ out,
                            int n) {
    int node = blockIdx.x * (blockDim.x >> 5) + (threadIdx.x >> 5);
    int lane = threadIdx.x & 31;
    if (node >= n) return;

    const uint2* __restrict__ h2 = (const uint2*)g_hh;  // node*32 + lane

    float dv = g_dinv[node];
    float sd = dv * dv;
    uint2 us = h2[(size_t)node * 32 + lane];
    float2 s0 = __half22float2(*(__half2*)&us.x);
    float2 s1 = __half22float2(*(__half2*)&us.y);
    float4 acc = make_float4(s0.x * sd, s0.y * sd, s1.x * sd, s1.y * sd);

    int i = g_off[node];
    int end = g_off[node + 1];
    for (; i + 4 <= end; i += 4) {
        int2 e0 = g_edge[i + 0], e1 = g_edge[i + 1];
        int2 e2 = g_edge[i + 2], e3 = g_edge[i + 3];
        uint2 u0 = h2[(size_t)e0.x * 32 + lane];
        uint2 u1 = h2[(size_t)e1.x * 32 + lane];
        uint2 u2 = h2[(size_t)e2.x * 32 + lane];
        uint2 u3 = h2[(size_t)e3.x * 32 + lane];
        float w0 = __int_as_float(e0.y), w1 = __int_as_float(e1.y);
        float w2 = __int_as_float(e2.y), w3 = __int_as_float(e3.y);
        float2 a0 = __half22float2(*(__half2*)&u0.x), b0 = __half22float2(*(__half2*)&u0.y);
        float2 a1 = __half22float2(*(__half2*)&u1.x), b1 = __half22float2(*(__half2*)&u1.y);
        float2 a2 = __half22float2(*(__half2*)&u2.x), b2 = __half22float2(*(__half2*)&u2.y);
        float2 a3 = __half22float2(*(__half2*)&u3.x), b3 = __half22float2(*(__half2*)&u3.y);
        acc.x += a0.x * w0 + a1.x * w1 + a2.x * w2 + a3.x * w3;
        acc.y += a0.y * w0 + a1.y * w1 + a2.y * w2 + a3.y * w3;
        acc.z += b0.x * w0 + b1.x * w1 + b2.x * w2 + b3.x * w3;
        acc.w += b0.y * w0 + b1.y * w1 + b2.y * w2 + b3.y * w3;
    }
    for (; i < end; i++) {
        int2 e0 = g_edge[i];
        float w = __int_as_float(e0.y);
        uint2 u0 = h2[(size_t)e0.x * 32 + lane];
        float2 a0 = __half22float2(*(__half2*)&u0.x);
        float2 b0 = __half22float2(*(__half2*)&u0.y);
        acc.x += a0.x * w; acc.y += a0.y * w;
        acc.z += b0.x * w; acc.w += b0.y * w;
    }

    float4 bb = ((const float4*)b)[lane];
    float4 o = make_float4(acc.x + bb.x, acc.y + bb.y,
                           acc.z + bb.z, acc.w + bb.w);
    ((float4*)out)[(size_t)node * 32 + lane] = o;
}

// ---------------------------------------------------------------------------
extern "C" void kernel_launch(void* const* d_in, const int* in_sizes, int n_in,
                              void* d_out, int out_size) {
    const float* x  = (const float*)d_in[0];
    const float* W  = (const float*)d_in[1];
    const float* b  = (const float*)d_in[2];
    const float* ew = (const float*)d_in[3];
    const int* eidx = (const int*)d_in[4];
    float* out = (float*)d_out;

    int n = in_sizes[0] / D;
    int e = in_sizes[3];
    const int* src = eidx;
    const int* dst = eidx + e;

    static cudaStream_t s1 = nullptr;
    static cudaEvent_t ev_fork = nullptr, ev_gemm = nullptr;
    if (s1 == nullptr) {
        cudaStreamCreateWithFlags(&s1, cudaStreamNonBlocking);
        cudaEventCreateWithFlags(&ev_fork, cudaEventDisableTiming);
        cudaEventCreateWithFlags(&ev_gemm, cudaEventDisableTiming);
    }

    // branch A: gemm on s1 (depends only on x, W)
    cudaEventRecord(ev_fork, 0);
    cudaStreamWaitEvent(s1, ev_fork, 0);
    k_gemm<<<(n + BM - 1) / BM, 256, 0, s1>>>(x, W, n);
    cudaEventRecord(ev_gemm, s1);

    // main chain: init -> edge(hist+deg) -> scan(+dinv) -> build
    k_init<<<(n + 255) / 256, 256>>>(n);
    k_edge<<<(e / 4 + 255) / 256, 256>>>(ew, dst, e);
    k_scan<<<1, 1024>>>(n);
    k_build<<<(e + 255) / 256, 256>>>(ew, src, dst, e);

    // join gemm, then aggregate
    cudaStreamWaitEvent(0, ev_gemm, 0);
    k_aggregate<<<(n + 7) / 8, 256>>>(b, out, n);
}

// round 7
// speedup vs baseline: 1.0152x; 1.0152x over previous
#include <cuda_runtime.h>
#include <cuda_fp16.h>

// GCNConv, CSR-gather, fp16 features, self-restoring state (no init kernel):
//   s1 : k_gemm      h_half = fp16(x @ W^T)
//   s0 : k_edge      rank[i]=atomicAdd(cnt[dst]); atomicAdd(deg[dst], ew)
//        k_scan      1-block shfl scan cnt -> off; zeroes cnt behind itself
//        k_build     edge[off[dst]+rank] = {src, rsqrt(1+deg_s)*ew*rsqrt(1+deg_d)}
//   join k_aggregate out = h[i]/(1+deg) + sum h[src]*w + b ; resets deg=0
//
// Invariant: g_cnt == 0 and g_deg == 0 at entry (static zero-init; each call
// restores both), so the pipeline is deterministic across graph replays.

#define MAX_NODES 10016
#define MAX_EDGES 650000
#define D 128

__device__ float  g_deg[MAX_NODES];          // zero at entry, zeroed by aggregate
__device__ __half g_hh[(size_t)MAX_NODES * D];
__device__ int    g_cnt[MAX_NODES];          // zero at entry, zeroed by scan
__device__ int    g_off[MAX_NODES + 1];
__device__ int    g_rank[MAX_EDGES];
__device__ int2   g_edge[MAX_EDGES];         // {src, float_bits(norm weight)}

// ---------------------------------------------------------------------------
// Fused histogram (rank capture) + weighted degree. 4 edges per thread.
__global__ void k_edge(const float* __restrict__ ew,
                       const int* __restrict__ dst, int e) {
    int i4 = (blockIdx.x * blockDim.x + threadIdx.x) * 4;
    if (i4 + 3 < e) {
        int4 d = *(const int4*)&dst[i4];
        float4 w = *(const float4*)&ew[i4];
        g_rank[i4 + 0] = atomicAdd(&g_cnt[d.x], 1);
        g_rank[i4 + 1] = atomicAdd(&g_cnt[d.y], 1);
        g_rank[i4 + 2] = atomicAdd(&g_cnt[d.z], 1);
        g_rank[i4 + 3] = atomicAdd(&g_cnt[d.w], 1);
        atomicAdd(&g_deg[d.x], w.x);
        atomicAdd(&g_deg[d.y], w.y);
        atomicAdd(&g_deg[d.z], w.z);
        atomicAdd(&g_deg[d.w], w.w);
    } else {
        for (int i = i4; i < e; i++) {
            int d = dst[i];
            g_rank[i] = atomicAdd(&g_cnt[d], 1);
            atomicAdd(&g_deg[d], ew[i]);
        }
    }
}

// Single-block pure int scan; zeroes cnt as it reads. 2 barriers total.
#define CHUNK 10   // 1024*10 = 10240 >= MAX_NODES
__global__ void k_scan(int n) {
    int tid = threadIdx.x;
    int lane = tid & 31, wid = tid >> 5;
    int base = tid * CHUNK;

    int v[CHUNK];
    int sum = 0;
#pragma unroll
    for (int j = 0; j < CHUNK; j++) {
        int i = base + j;
        int c = (i < n) ? g_cnt[i] : 0;
        if (i < n) g_cnt[i] = 0;          // restore invariant for next call
        v[j] = sum;
        sum += c;
    }
    int s = sum;
#pragma unroll
    for (int o = 1; o < 32; o <<= 1) {
        int t = __shfl_up_sync(0xffffffffu, s, o);
        if (lane >= o) s += t;
    }
    __shared__ int wsum[32];
    if (lane == 31) wsum[wid] = s;
    __syncthreads();
    if (wid == 0) {
        int w = wsum[lane];
#pragma unroll
        for (int o = 1; o < 32; o <<= 1) {
            int t = __shfl_up_sync(0xffffffffu, w, o);
            if (lane >= o) w += t;
        }
        wsum[lane] = w;
    }
    __syncthreads();
    int excl = s - sum + (wid > 0 ? wsum[wid - 1] : 0);
#pragma unroll
    for (int j = 0; j < CHUNK; j++) {
        int i = base + j;
        if (i < n) g_off[i] = excl + v[j];
    }
    if (tid == 1023) g_off[n] = excl + sum;
}

// Atomic-free CSR scatter with folded normalization, 2 edges per thread.
__global__ void k_build(const float* __restrict__ ew,
                        const int* __restrict__ src,
                        const int* __restrict__ dst, int e) {
    int i2 = (blockIdx.x * blockDim.x + threadIdx.x) * 2;
    if (i2 + 1 < e) {
        int2 s = *(const int2*)&src[i2];
        int2 d = *(const int2*)&dst[i2];
        float2 w = *(const float2*)&ew[i2];
        int2 r = *(const int2*)&g_rank[i2];
        float n0 = rsqrtf(1.0f + g_deg[s.x]) * w.x * rsqrtf(1.0f + g_deg[d.x]);
        float n1 = rsqrtf(1.0f + g_deg[s.y]) * w.y * rsqrtf(1.0f + g_deg[d.y]);
        g_edge[g_off[d.x] + r.x] = make_int2(s.x, __float_as_int(n0));
        g_edge[g_off[d.y] + r.y] = make_int2(s.y, __float_as_int(n1));
    } else if (i2 < e) {
        int i = i2;
        int s = src[i], d = dst[i];
        float w = rsqrtf(1.0f + g_deg[s]) * ew[i] * rsqrtf(1.0f + g_deg[d]);
        g_edge[g_off[d] + g_rank[i]] = make_int2(s, __float_as_int(w));
    }
}

// ---------------------------------------------------------------------------
// h = fp16(x @ W^T).  64 nodes x 128 dims per block, BK=16, 256 threads.
#define BM 64
#define BK 16
#define XS_LD 68
#define WS_LD 132
__global__ void k_gemm(const float* __restrict__ x, const float* __restrict__ W,
                       int n) {
    __shared__ float xs[BK][XS_LD];
    __shared__ float ws[BK][WS_LD];
    int t = threadIdx.x;
    int c = t & 31;
    int r = t >> 5;
    int node0 = blockIdx.x * BM;

    float acc[8][4];
#pragma unroll
    for (int j = 0; j < 8; j++)
#pragma unroll
        for (int i = 0; i < 4; i++) acc[j][i] = 0.0f;

    for (int k0 = 0; k0 < D; k0 += BK) {
        {
            int nn = t >> 2;
            int ks = (t & 3) * 4;
            int gn = node0 + nn;
            float4 v = make_float4(0.f, 0.f, 0.f, 0.f);
            if (gn < n) v = *(const float4*)&x[(size_t)gn * D + k0 + ks];
            xs[ks + 0][nn] = v.x; xs[ks + 1][nn] = v.y;
            xs[ks + 2][nn] = v.z; xs[ks + 3][nn] = v.w;
        }
#pragma unroll
        for (int q = 0; q < 2; q++) {
            int f = t * 2 + q;
            int dim = f >> 2;
            int ks = (f & 3) * 4;
            float4 v = *(const float4*)&W[(size_t)dim * D + k0 + ks];
            ws[ks + 0][dim] = v.x; ws[ks + 1][dim] = v.y;
            ws[ks + 2][dim] = v.z; ws[ks + 3][dim] = v.w;
        }
        __syncthreads();
#pragma unroll
        for (int kk = 0; kk < BK; kk++) {
            float4 wv = *(const float4*)&ws[kk][c * 4];
            float4 xa = *(const float4*)&xs[kk][r * 8];
            float4 xb = *(const float4*)&xs[kk][r * 8 + 4];
            float xn[8] = {xa.x, xa.y, xa.z, xa.w, xb.x, xb.y, xb.z, xb.w};
#pragma unroll
            for (int j = 0; j < 8; j++) {
                acc[j][0] += xn[j] * wv.x;
                acc[j][1] += xn[j] * wv.y;
                acc[j][2] += xn[j] * wv.z;
                acc[j][3] += xn[j] * wv.w;
            }
        }
        __syncthreads();
    }
#pragma unroll
    for (int j = 0; j < 8; j++) {
        int gn = node0 + r * 8 + j;
        if (gn < n) {
            __half2 p0 = __floats2half2_rn(acc[j][0], acc[j][1]);
            __half2 p1 = __floats2half2_rn(acc[j][2], acc[j][3]);
            uint2 u;
            u.x = *(unsigned int*)&p0;
            u.y = *(unsigned int*)&p1;
            ((uint2*)(g_hh + (size_t)gn * D))[c] = u;
        }
    }
}

// ---------------------------------------------------------------------------
// One warp per destination node; fp32 accumulator, fp16 gathers (8B/lane).
// Lane 0 resets deg[node] = 0 for the next invocation.
__global__ void k_aggregate(const float* __restrict__ b, float* __restrict__ out,
                            int n) {
    int node = blockIdx.x * (blockDim.x >> 5) + (threadIdx.x >> 5);
    int lane = threadIdx.x & 31;
    if (node >= n) return;

    const uint2* __restrict__ h2 = (const uint2*)g_hh;

    float dg = g_deg[node];
    if (lane == 0) g_deg[node] = 0.0f;      // restore invariant
    float sd = __fdividef(1.0f, 1.0f + dg); // dinv^2 for the self-loop

    uint2 us = h2[(size_t)node * 32 + lane];
    float2 s0 = __half22float2(*(__half2*)&us.x);
    float2 s1 = __half22float2(*(__half2*)&us.y);
    float4 acc = make_float4(s0.x * sd, s0.y * sd, s1.x * sd, s1.y * sd);

    int i = g_off[node];
    int end = g_off[node + 1];
    for (; i + 4 <= end; i += 4) {
        int2 e0 = g_edge[i + 0], e1 = g_edge[i + 1];
        int2 e2 = g_edge[i + 2], e3 = g_edge[i + 3];
        uint2 u0 = h2[(size_t)e0.x * 32 + lane];
        uint2 u1 = h2[(size_t)e1.x * 32 + lane];
        uint2 u2 = h2[(size_t)e2.x * 32 + lane];
        uint2 u3 = h2[(size_t)e3.x * 32 + lane];
        float w0 = __int_as_float(e0.y), w1 = __int_as_float(e1.y);
        float w2 = __int_as_float(e2.y), w3 = __int_as_float(e3.y);
        float2 a0 = __half22float2(*(__half2*)&u0.x), b0 = __half22float2(*(__half2*)&u0.y);
        float2 a1 = __half22float2(*(__half2*)&u1.x), b1 = __half22float2(*(__half2*)&u1.y);
        float2 a2 = __half22float2(*(__half2*)&u2.x), b2 = __half22float2(*(__half2*)&u2.y);
        float2 a3 = __half22float2(*(__half2*)&u3.x), b3 = __half22float2(*(__half2*)&u3.y);
        acc.x += a0.x * w0 + a1.x * w1 + a2.x * w2 + a3.x * w3;
        acc.y += a0.y * w0 + a1.y * w1 + a2.y * w2 + a3.y * w3;
        acc.z += b0.x * w0 + b1.x * w1 + b2.x * w2 + b3.x * w3;
        acc.w += b0.y * w0 + b1.y * w1 + b2.y * w2 + b3.y * w3;
    }
    for (; i < end; i++) {
        int2 e0 = g_edge[i];
        float w = __int_as_float(e0.y);
        uint2 u0 = h2[(size_t)e0.x * 32 + lane];
        float2 a0 = __half22float2(*(__half2*)&u0.x);
        float2 b0 = __half22float2(*(__half2*)&u0.y);
        acc.x += a0.x * w; acc.y += a0.y * w;
        acc.z += b0.x * w; acc.w += b0.y * w;
    }

    float4 bb = ((const float4*)b)[lane];
    float4 o = make_float4(acc.x + bb.x, acc.y + bb.y,
                           acc.z + bb.z, acc.w + bb.w);
    ((float4*)out)[(size_t)node * 32 + lane] = o;
}

// ---------------------------------------------------------------------------
extern "C" void kernel_launch(void* const* d_in, const int* in_sizes, int n_in,
                              void* d_out, int out_size) {
    const float* x  = (const float*)d_in[0];
    const float* W  = (const float*)d_in[1];
    const float* b  = (const float*)d_in[2];
    const float* ew = (const float*)d_in[3];
    const int* eidx = (const int*)d_in[4];
    float* out = (float*)d_out;

    int n = in_sizes[0] / D;
    int e = in_sizes[3];
    const int* src = eidx;
    const int* dst = eidx + e;

    static cudaStream_t s1 = nullptr;
    static cudaEvent_t ev_fork = nullptr, ev_gemm = nullptr;
    if (s1 == nullptr) {
        cudaStreamCreateWithFlags(&s1, cudaStreamNonBlocking);
        cudaEventCreateWithFlags(&ev_fork, cudaEventDisableTiming);
        cudaEventCreateWithFlags(&ev_gemm, cudaEventDisableTiming);
    }

    // branch A: gemm on s1 (depends only on x, W)
    cudaEventRecord(ev_fork, 0);
    cudaStreamWaitEvent(s1, ev_fork, 0);
    k_gemm<<<(n + BM - 1) / BM, 256, 0, s1>>>(x, W, n);
    cudaEventRecord(ev_gemm, s1);

    // main chain: edge(hist+deg) -> scan -> build
    k_edge<<<(e / 4 + 255) / 256, 256>>>(ew, dst, e);
    k_scan<<<1, 1024>>>(n);
    k_build<<<(e / 2 + 255) / 256, 256>>>(ew, src, dst, e);

    // join gemm, then aggregate
    cudaStreamWaitEvent(0, ev_gemm, 0);
    k_aggregate<<<(n + 7) / 8, 256>>>(b, out, n);
}

// round 8
// speedup vs baseline: 1.0546x; 1.0389x over previous
#include <cuda_runtime.h>
#include <cuda_fp16.h>

// GCNConv, CSR-gather, fp16 features. Degree computed FROM the CSR (no float
// atomics anywhere; k_edge does only the int histogram):
//   s1 : k_gemm      h = fp16(x @ W^T)
//   s0 : k_edge      rank[i] = atomicAdd(cnt[dst], 1)        (int atomics only)
//        k_scan      1-block shfl scan cnt -> off; zeroes cnt behind itself
//        k_build     edge[off[dst]+rank] = {src, raw ew}     (no atomics)
//        k_csrdeg    dinv[i] = rsqrt(1 + sum CSR ew)         (warp reduce)
//   join k_aggregate out = dinv_d*(h_self*dinv_d + sum ew*dinv_s*h_src) + b
//
// Invariant: g_cnt == 0 at entry (static zero-init; scan restores it).

#define MAX_NODES 10016
#define MAX_EDGES 650000
#define D 128

__device__ float  g_dinv[MAX_NODES];
__device__ __half g_hh[(size_t)MAX_NODES * D];
__device__ int    g_cnt[MAX_NODES];          // zero at entry, re-zeroed by scan
__device__ int    g_off[MAX_NODES + 1];
__device__ int    g_rank[MAX_EDGES];
__device__ int2   g_edge[MAX_EDGES];         // {src, float_bits(raw ew)}

// ---------------------------------------------------------------------------
// Histogram with rank capture. 4 edges per thread, int atomics only.
__global__ void k_edge(const int* __restrict__ dst, int e) {
    int i4 = (blockIdx.x * blockDim.x + threadIdx.x) * 4;
    if (i4 + 3 < e) {
        int4 d = *(const int4*)&dst[i4];
        int4 r;
        r.x = atomicAdd(&g_cnt[d.x], 1);
        r.y = atomicAdd(&g_cnt[d.y], 1);
        r.z = atomicAdd(&g_cnt[d.z], 1);
        r.w = atomicAdd(&g_cnt[d.w], 1);
        *(int4*)&g_rank[i4] = r;
    } else {
        for (int i = i4; i < e; i++)
            g_rank[i] = atomicAdd(&g_cnt[dst[i]], 1);
    }
}

// Single-block pure int scan; zeroes cnt as it reads. 2 barriers total.
#define CHUNK 10   // 1024*10 = 10240 >= MAX_NODES
__global__ void k_scan(int n) {
    int tid = threadIdx.x;
    int lane = tid & 31, wid = tid >> 5;
    int base = tid * CHUNK;

    int v[CHUNK];
    int sum = 0;
#pragma unroll
    for (int j = 0; j < CHUNK; j++) {
        int i = base + j;
        int c = (i < n) ? g_cnt[i] : 0;
        if (i < n) g_cnt[i] = 0;          // restore invariant
        v[j] = sum;
        sum += c;
    }
    int s = sum;
#pragma unroll
    for (int o = 1; o < 32; o <<= 1) {
        int t = __shfl_up_sync(0xffffffffu, s, o);
        if (lane >= o) s += t;
    }
    __shared__ int wsum[32];
    if (lane == 31) wsum[wid] = s;
    __syncthreads();
    if (wid == 0) {
        int w = wsum[lane];
#pragma unroll
        for (int o = 1; o < 32; o <<= 1) {
            int t = __shfl_up_sync(0xffffffffu, w, o);
            if (lane >= o) w += t;
        }
        wsum[lane] = w;
    }
    __syncthreads();
    int excl = s - sum + (wid > 0 ? wsum[wid - 1] : 0);
#pragma unroll
    for (int j = 0; j < CHUNK; j++) {
        int i = base + j;
        if (i < n) g_off[i] = excl + v[j];
    }
    if (tid == 1023) g_off[n] = excl + sum;
}

// Atomic-free CSR scatter of raw edges, 2 edges per thread.
__global__ void k_build(const float* __restrict__ ew,
                        const int* __restrict__ src,
                        const int* __restrict__ dst, int e) {
    int i2 = (blockIdx.x * blockDim.x + threadIdx.x) * 2;
    if (i2 + 1 < e) {
        int2 s = *(const int2*)&src[i2];
        int2 d = *(const int2*)&dst[i2];
        float2 w = *(const float2*)&ew[i2];
        int2 r = *(const int2*)&g_rank[i2];
        g_edge[g_off[d.x] + r.x] = make_int2(s.x, __float_as_int(w.x));
        g_edge[g_off[d.y] + r.y] = make_int2(s.y, __float_as_int(w.y));
    } else if (i2 < e) {
        g_edge[g_off[dst[i2]] + g_rank[i2]] =
            make_int2(src[i2], __float_as_int(ew[i2]));
    }
}

// dinv[i] = rsqrt(1 + sum of CSR weights). One warp per node; sequential reads.
__global__ void k_csrdeg(int n) {
    int node = blockIdx.x * (blockDim.x >> 5) + (threadIdx.x >> 5);
    int lane = threadIdx.x & 31;
    if (node >= n) return;
    int beg = g_off[node], end = g_off[node + 1];
    float s = 0.0f;
    for (int i = beg + lane; i < end; i += 32)
        s += __int_as_float(g_edge[i].y);
#pragma unroll
    for (int o = 16; o > 0; o >>= 1)
        s += __shfl_xor_sync(0xffffffffu, s, o);
    if (lane == 0) g_dinv[node] = rsqrtf(1.0f + s);
}

// ---------------------------------------------------------------------------
// h = fp16(x @ W^T).  64 nodes x 128 dims per block, BK=16, 256 threads.
#define BM 64
#define BK 16
#define XS_LD 68
#define WS_LD 132
__global__ void k_gemm(const float* __restrict__ x, const float* __restrict__ W,
                       int n) {
    __shared__ float xs[BK][XS_LD];
    __shared__ float ws[BK][WS_LD];
    int t = threadIdx.x;
    int c = t & 31;
    int r = t >> 5;
    int node0 = blockIdx.x * BM;

    float acc[8][4];
#pragma unroll
    for (int j = 0; j < 8; j++)
#pragma unroll
        for (int i = 0; i < 4; i++) acc[j][i] = 0.0f;

    for (int k0 = 0; k0 < D; k0 += BK) {
        {
            int nn = t >> 2;
            int ks = (t & 3) * 4;
            int gn = node0 + nn;
            float4 v = make_float4(0.f, 0.f, 0.f, 0.f);
            if (gn < n) v = *(const float4*)&x[(size_t)gn * D + k0 + ks];
            xs[ks + 0][nn] = v.x; xs[ks + 1][nn] = v.y;
            xs[ks + 2][nn] = v.z; xs[ks + 3][nn] = v.w;
        }
#pragma unroll
        for (int q = 0; q < 2; q++) {
            int f = t * 2 + q;
            int dim = f >> 2;
            int ks = (f & 3) * 4;
            float4 v = *(const float4*)&W[(size_t)dim * D + k0 + ks];
            ws[ks + 0][dim] = v.x; ws[ks + 1][dim] = v.y;
            ws[ks + 2][dim] = v.z; ws[ks + 3][dim] = v.w;
        }
        __syncthreads();
#pragma unroll
        for (int kk = 0; kk < BK; kk++) {
            float4 wv = *(const float4*)&ws[kk][c * 4];
            float4 xa = *(const float4*)&xs[kk][r * 8];
            float4 xb = *(const float4*)&xs[kk][r * 8 + 4];
            float xn[8] = {xa.x, xa.y, xa.z, xa.w, xb.x, xb.y, xb.z, xb.w};
#pragma unroll
            for (int j = 0; j < 8; j++) {
                acc[j][0] += xn[j] * wv.x;
                acc[j][1] += xn[j] * wv.y;
                acc[j][2] += xn[j] * wv.z;
                acc[j][3] += xn[j] * wv.w;
            }
        }
        __syncthreads();
    }
#pragma unroll
    for (int j = 0; j < 8; j++) {
        int gn = node0 + r * 8 + j;
        if (gn < n) {
            __half2 p0 = __floats2half2_rn(acc[j][0], acc[j][1]);
            __half2 p1 = __floats2half2_rn(acc[j][2], acc[j][3]);
            uint2 u;
            u.x = *(unsigned int*)&p0;
            u.y = *(unsigned int*)&p1;
            ((uint2*)(g_hh + (size_t)gn * D))[c] = u;
        }
    }
}

// ---------------------------------------------------------------------------
// One warp per destination node; fp32 accumulator, fp16 gathers (8B/lane).
// Per-edge weight: ew * dinv[src] (warp-broadcast 4B load, L1-resident).
// Final scale by dinv[node].
__global__ void k_aggregate(const float* __restrict__ b, float* __restrict__ out,
                            int n) {
    int node = blockIdx.x * (blockDim.x >> 5) + (threadIdx.x >> 5);
    int lane = threadIdx.x & 31;
    if (node >= n) return;

    const uint2* __restrict__ h2 = (const uint2*)g_hh;
    float dv = g_dinv[node];

    uint2 us = h2[(size_t)node * 32 + lane];
    float2 s0 = __half22float2(*(__half2*)&us.x);
    float2 s1 = __half22float2(*(__half2*)&us.y);
    // acc = h_self * dinv_d + sum ew*dinv_s*h_src ; out = dinv_d*acc + b
    float4 acc = make_float4(s0.x * dv, s0.y * dv, s1.x * dv, s1.y * dv);

    int i = g_off[node];
    int end = g_off[node + 1];
    for (; i + 4 <= end; i += 4) {
        int2 e0 = g_edge[i + 0], e1 = g_edge[i + 1];
        int2 e2 = g_edge[i + 2], e3 = g_edge[i + 3];
        uint2 u0 = h2[(size_t)e0.x * 32 + lane];
        uint2 u1 = h2[(size_t)e1.x * 32 + lane];
        uint2 u2 = h2[(size_t)e2.x * 32 + lane];
        uint2 u3 = h2[(size_t)e3.x * 32 + lane];
        float w0 = __int_as_float(e0.y) * g_dinv[e0.x];
        float w1 = __int_as_float(e1.y) * g_dinv[e1.x];
        float w2 = __int_as_float(e2.y) * g_dinv[e2.x];
        float w3 = __int_as_float(e3.y) * g_dinv[e3.x];
        float2 a0 = __half22float2(*(__half2*)&u0.x), b0 = __half22float2(*(__half2*)&u0.y);
        float2 a1 = __half22float2(*(__half2*)&u1.x), b1 = __half22float2(*(__half2*)&u1.y);
        float2 a2 = __half22float2(*(__half2*)&u2.x), b2 = __half22float2(*(__half2*)&u2.y);
        float2 a3 = __half22float2(*(__half2*)&u3.x), b3 = __half22float2(*(__half2*)&u3.y);
        acc.x += a0.x * w0 + a1.x * w1 + a2.x * w2 + a3.x * w3;
        acc.y += a0.y * w0 + a1.y * w1 + a2.y * w2 + a3.y * w3;
        acc.z += b0.x * w0 + b1.x * w1 + b2.x * w2 + b3.x * w3;
        acc.w += b0.y * w0 + b1.y * w1 + b2.y * w2 + b3.y * w3;
    }
    for (; i < end; i++) {
        int2 e0 = g_edge[i];
        float w = __int_as_float(e0.y) * g_dinv[e0.x];
        uint2 u0 = h2[(size_t)e0.x * 32 + lane];
        float2 a0 = __half22float2(*(__half2*)&u0.x);
        float2 b0 = __half22float2(*(__half2*)&u0.y);
        acc.x += a0.x * w; acc.y += a0.y * w;
        acc.z += b0.x * w; acc.w += b0.y * w;
    }

    float4 bb = ((const float4*)b)[lane];
    float4 o = make_float4(acc.x * dv + bb.x, acc.y * dv + bb.y,
                           acc.z * dv + bb.z, acc.w * dv + bb.w);
    ((float4*)out)[(size_t)node * 32 + lane] = o;
}

// ---------------------------------------------------------------------------
extern "C" void kernel_launch(void* const* d_in, const int* in_sizes, int n_in,
                              void* d_out, int out_size) {
    const float* x  = (const float*)d_in[0];
    const float* W  = (const float*)d_in[1];
    const float* b  = (const float*)d_in[2];
    const float* ew = (const float*)d_in[3];
    const int* eidx = (const int*)d_in[4];
    float* out = (float*)d_out;

    int n = in_sizes[0] / D;
    int e = in_sizes[3];
    const int* src = eidx;
    const int* dst = eidx + e;

    static cudaStream_t s1 = nullptr;
    static cudaEvent_t ev_fork = nullptr, ev_gemm = nullptr;
    if (s1 == nullptr) {
        cudaStreamCreateWithFlags(&s1, cudaStreamNonBlocking);
        cudaEventCreateWithFlags(&ev_fork, cudaEventDisableTiming);
        cudaEventCreateWithFlags(&ev_gemm, cudaEventDisableTiming);
    }

    // branch A: gemm on s1 (depends only on x, W)
    cudaEventRecord(ev_fork, 0);
    cudaStreamWaitEvent(s1, ev_fork, 0);
    k_gemm<<<(n + BM - 1) / BM, 256, 0, s1>>>(x, W, n);
    cudaEventRecord(ev_gemm, s1);

    // main chain: edge(hist) -> scan -> build(raw) -> csrdeg(dinv)
    k_edge<<<(e / 4 + 255) / 256, 256>>>(dst, e);
    k_scan<<<1, 1024>>>(n);
    k_build<<<(e / 2 + 255) / 256, 256>>>(ew, src, dst, e);
    k_csrdeg<<<(n + 7) / 8, 256>>>(n);

    // join gemm, then aggregate
    cudaStreamWaitEvent(0, ev_gemm, 0);
    k_aggregate<<<(n + 7) / 8, 256>>>(b, out, n);
}